// round 16
// baseline (speedup 1.0000x reference)
#include <cuda_runtime.h>
#include <math.h>

#define BATCH 256
#define NV 27
#define DMODEL 256
#define FFDIM 1024
#define NLAYERS 3
#define THREADS 1024

#define LDR 260            // activation row pitch (floats)
#define OFF_T 0
#define OFF_A (32 * LDR)
#define OFF_Q (2 * 32 * LDR)
#define OFF_K (3 * 32 * LDR)
#define OFF_V (4 * 32 * LDR)
#define SMEM_FLOATS (5 * 32 * LDR)
#define SMEM_BYTES (SMEM_FLOATS * 4 + 2 * 27 * 28 + 64)

// 36 weight blocks of [256x256], fragment-packed for the 1024-thread mapping:
// float4 index within block: kt*1024 + tid
//   tid -> warp=tid>>5 (owns cols [8w,8w+8)), grp=(tid&31)>>2, quad=tid&3
//   v = { B[kt*16+quad  ][w*8+grp], B[kt*16+quad+4][w*8+grp],      (ks2=0)
//         B[kt*16+8+quad][w*8+grp], B[kt*16+8+quad+4][w*8+grp] }   (ks2=1)
#define BLK_F4 16384                   // 16 kt * 1024 tid
__device__ float4 g_wpack[36 * BLK_F4];
__device__ int    g_mode;
__device__ float  g_zero[DMODEL];      // zero-initialized

// ---------------- mask dtype sniffer ----------------------------------------
__global__ void detect_kernel(const unsigned char* __restrict__ km) {
    __shared__ int cnt1, cnt3f;
    if (threadIdx.x == 0) { cnt1 = 0; cnt3f = 0; }
    __syncthreads();
    int l1 = 0, l3 = 0;
    for (int i = threadIdx.x; i < (BATCH * NV) / 4; i += blockDim.x) {
        if (km[4 * i + 1] != 0) l1++;
        if (km[4 * i + 3] == 0x3F) l3++;
    }
    atomicAdd(&cnt1, l1);
    atomicAdd(&cnt3f, l3);
    __syncthreads();
    if (threadIdx.x == 0) {
        if (cnt1 > 0)       g_mode = 0;  // uint8 bool
        else if (cnt3f > 0) g_mode = 2;  // float32
        else                g_mode = 1;  // int32
    }
}

// ---------------- weight repack: [256x256] blocks -> fragment order ----------
__global__ void repack_kernel(const float* __restrict__ Wq,
                              const float* __restrict__ Wk,
                              const float* __restrict__ Wv,
                              const float* __restrict__ Wo,
                              const float* __restrict__ W1,
                              const float* __restrict__ W2) {
    int gid = blockIdx.x * 256 + threadIdx.x;       // 36*16384 = 589824 total
    if (gid >= 36 * BLK_F4) return;
    int blk = gid >> 14;
    int rem = gid & (BLK_F4 - 1);
    int kt  = rem >> 10;
    int tid = rem & 1023;
    int layer = blk / 12, idx = blk % 12;

    const float* src;
    int ldB;
    if (idx < 4) {
        const float* base = (idx == 0) ? Wq : (idx == 1) ? Wk
                          : (idx == 2) ? Wv : Wo;
        src = base + (size_t)layer * DMODEL * DMODEL;
        ldB = DMODEL;
    } else if (idx < 8) {
        src = W1 + (size_t)layer * DMODEL * FFDIM + (idx - 4) * 256;
        ldB = FFDIM;
    } else {
        src = W2 + (size_t)layer * FFDIM * DMODEL + (size_t)(idx - 8) * 256 * DMODEL;
        ldB = DMODEL;
    }

    int warp = tid >> 5, lane = tid & 31;
    int grp = lane >> 2, quad = lane & 3;
    int n = warp * 8 + grp;
    int k0 = kt * 16 + quad;
    float4 v;
    v.x = src[(size_t)k0 * ldB + n];
    v.y = src[(size_t)(k0 + 4) * ldB + n];
    v.z = src[(size_t)(k0 + 8) * ldB + n];
    v.w = src[(size_t)(k0 + 12) * ldB + n];
    g_wpack[gid] = v;
}

// ---------------- CTA GEMM: C[32x256] = A[32x256] @ Bpacked ------------------
// 32 warps, warp w owns cols [8w,8w+8). NO SMEM ring, NO k-loop barriers.
// One LDG.128 per warp-iteration (both ks2 B-pairs), prefetch depth 2.
// EPI: 0 = bias -> Cs ; 1 = Cs += acc + bias ; 2 = gelu(acc + bias) -> Cs
template <int EPI>
__device__ __noinline__ void cta_gemm(const float* __restrict__ Asm,
                                      int blk,
                                      const float* __restrict__ bias,
                                      float* __restrict__ Cs) {
    const float4* B = g_wpack + (size_t)blk * BLK_F4;

    int tid  = threadIdx.x;
    int lane = tid & 31;
    int warp = tid >> 5;          // 0..31
    int grp  = lane >> 2;
    int quad = lane & 3;

    float c[2][4];
    #pragma unroll
    for (int mi = 0; mi < 2; mi++)
        #pragma unroll
        for (int r = 0; r < 4; r++) c[mi][r] = 0.0f;

    float4 pre[2];
    pre[0] = __ldg(B + tid);
    pre[1] = __ldg(B + 1024 + tid);

    #pragma unroll
    for (int kt = 0; kt < 16; kt++) {
        float4 v = pre[kt & 1];
        if (kt + 2 < 16) pre[kt & 1] = __ldg(B + (kt + 2) * 1024 + tid);
        #pragma unroll
        for (int ks2 = 0; ks2 < 2; ks2++) {
            unsigned b0 = __float_as_uint(ks2 ? v.z : v.x);
            unsigned b1 = __float_as_uint(ks2 ? v.w : v.y);
            int kc = kt * 16 + ks2 * 8 + quad;
            #pragma unroll
            for (int mi = 0; mi < 2; mi++) {
                int m = mi * 16 + grp;
                unsigned a0 = __float_as_uint(Asm[m * LDR + kc]);
                unsigned a1 = __float_as_uint(Asm[(m + 8) * LDR + kc]);
                unsigned a2 = __float_as_uint(Asm[m * LDR + kc + 4]);
                unsigned a3 = __float_as_uint(Asm[(m + 8) * LDR + kc + 4]);
                asm volatile(
                    "mma.sync.aligned.m16n8k8.row.col.f32.tf32.tf32.f32 "
                    "{%0,%1,%2,%3}, {%4,%5,%6,%7}, {%8,%9}, {%0,%1,%2,%3};"
                    : "+f"(c[mi][0]), "+f"(c[mi][1]),
                      "+f"(c[mi][2]), "+f"(c[mi][3])
                    : "r"(a0), "r"(a1), "r"(a2), "r"(a3),
                      "r"(b0), "r"(b1));
            }
        }
    }

    __syncthreads();   // guard: all A-reads done before C writes (C may alias A)
    int colb = warp * 8 + quad * 2;
    float bia0 = bias[colb], bia1 = bias[colb + 1];
    #pragma unroll
    for (int mi = 0; mi < 2; mi++) {
        float v0 = c[mi][0] + bia0;
        float v1 = c[mi][1] + bia1;
        float v2 = c[mi][2] + bia0;
        float v3 = c[mi][3] + bia1;
        int r0 = mi * 16 + grp;
        int r1 = r0 + 8;
        int i0 = r0 * LDR + colb;
        int i1 = r1 * LDR + colb;
        const float is2 = 0.70710678118654752f;
        if (EPI == 0) {
            Cs[i0] = v0; Cs[i0 + 1] = v1;
            Cs[i1] = v2; Cs[i1 + 1] = v3;
        } else if (EPI == 1) {
            Cs[i0] += v0; Cs[i0 + 1] += v1;
            Cs[i1] += v2; Cs[i1 + 1] += v3;
        } else {
            Cs[i0]     = 0.5f * v0 * (1.0f + erff(v0 * is2));
            Cs[i0 + 1] = 0.5f * v1 * (1.0f + erff(v1 * is2));
            Cs[i1]     = 0.5f * v2 * (1.0f + erff(v2 * is2));
            Cs[i1 + 1] = 0.5f * v3 * (1.0f + erff(v3 * is2));
        }
    }
    __syncthreads();
}

// ---------------- CTA layernorm: 32 rows, 32 warps (1 row each) ---------------
__device__ __forceinline__ void cta_ln(const float* __restrict__ x,
                                       const float* __restrict__ g,
                                       const float* __restrict__ bta,
                                       float* __restrict__ y) {
    int tid = threadIdx.x, warp = tid >> 5, lane = tid & 31;
    int r = warp;
    const float* xr = x + r * LDR + lane * 8;
    float4 v0 = *(const float4*)&xr[0];
    float4 v1 = *(const float4*)&xr[4];
    float s  = v0.x + v0.y + v0.z + v0.w + v1.x + v1.y + v1.z + v1.w;
    float ss = v0.x*v0.x + v0.y*v0.y + v0.z*v0.z + v0.w*v0.w
             + v1.x*v1.x + v1.y*v1.y + v1.z*v1.z + v1.w*v1.w;
    #pragma unroll
    for (int off = 16; off > 0; off >>= 1) {
        s  += __shfl_xor_sync(0xffffffffu, s,  off);
        ss += __shfl_xor_sync(0xffffffffu, ss, off);
    }
    float mu  = s * (1.0f / DMODEL);
    float var = ss * (1.0f / DMODEL) - mu * mu;
    float rs  = rsqrtf(var + 1e-5f);
    float* yr = y + r * LDR;
    #pragma unroll
    for (int j = 0; j < 8; j++) {
        int cc = lane * 8 + j;
        float xv = (j < 4) ? ((const float*)&v0)[j] : ((const float*)&v1)[j - 4];
        yr[cc] = (xv - mu) * rs * g[cc] + bta[cc];
    }
}

// ---------------- attention (first 8 warps), two head-dim passes --------------
// Reads q from qb, writes output to ab. fp32 K/V. 64-reg safe (R14-proven).
__device__ __noinline__ void cta_attn(const float* __restrict__ qb,
                                      const float* __restrict__ kb,
                                      const float* __restrict__ vb,
                                      const unsigned char* __restrict__ msk,
                                      const unsigned char* __restrict__ nbrt,
                                      float* __restrict__ ab) {
    int tid  = threadIdx.x;
    int warp = tid >> 5;
    int r    = tid & 31;
    if (warp >= 8 || r >= NV) return;
    int h = warp;
    const float scale = 0.17677669529663687f;  // 1/sqrt(32)

    const unsigned char* mr = msk  + r * 28;
    const unsigned char* nr = nbrt + r * 28;

    float s[NV];
    #pragma unroll
    for (int l = 0; l < NV; l++) s[l] = 0.0f;

    #pragma unroll
    for (int half = 0; half < 2; half++) {
        float4 q4[4];
        #pragma unroll
        for (int i = 0; i < 4; i++)
            q4[i] = *(const float4*)&qb[r * LDR + h * 32 + half * 16 + i * 4];
        #pragma unroll
        for (int l = 0; l < NV; l++) {
            if (mr[l]) {
                const float* kr = &kb[nr[l] * LDR + h * 32 + half * 16];
                float acc = 0.0f;
                #pragma unroll
                for (int i = 0; i < 4; i++) {
                    float4 k4 = *(const float4*)&kr[i * 4];
                    acc += q4[i].x * k4.x + q4[i].y * k4.y
                         + q4[i].z * k4.z + q4[i].w * k4.w;
                }
                s[l] += acc;
            }
        }
    }
    float mx = -1e30f;
    #pragma unroll
    for (int l = 0; l < NV; l++)
        if (mr[l]) { s[l] *= scale; mx = fmaxf(mx, s[l]); }
    float sum = 0.0f;
    #pragma unroll
    for (int l = 0; l < NV; l++) {
        float w = mr[l] ? expf(s[l] - mx) : 0.0f;
        s[l] = w;
        sum += w;
    }
    float inv = (sum > 0.0f) ? (1.0f / sum) : 0.0f;

    #pragma unroll
    for (int half = 0; half < 2; half++) {
        float o[16];
        #pragma unroll
        for (int i = 0; i < 16; i++) o[i] = 0.0f;
        #pragma unroll
        for (int l = 0; l < NV; l++) {
            if (s[l] > 0.0f) {
                const float* vr = &vb[nr[l] * LDR + h * 32 + half * 16];
                float w = s[l];
                #pragma unroll
                for (int i = 0; i < 16; i++) o[i] += w * vr[i];
            }
        }
        #pragma unroll
        for (int i = 0; i < 16; i++)
            ab[r * LDR + h * 32 + half * 16 + i] = o[i] * inv;
    }
}

// ---------------- megakernel: one CTA per patch, 32 warps ---------------------
__global__ void __launch_bounds__(THREADS, 1)
mega_kernel(const float* __restrict__ patch, const void* __restrict__ km_raw,
            const float* __restrict__ w_in, const float* __restrict__ b_in,
            const float* __restrict__ pos,
            const float* __restrict__ ln1_g, const float* __restrict__ ln1_b,
            const float* __restrict__ ln2_g, const float* __restrict__ ln2_b,
            const float* __restrict__ bq, const float* __restrict__ bk,
            const float* __restrict__ bv, const float* __restrict__ bo,
            const float* __restrict__ b1, const float* __restrict__ b2,
            const float* __restrict__ w_out, const float* __restrict__ b_out,
            float* __restrict__ out) {
    extern __shared__ float sm[];
    float* t  = sm + OFF_T;
    float* ab = sm + OFF_A;
    float* qb = sm + OFF_Q;
    float* kb = sm + OFF_K;
    float* vb = sm + OFF_V;
    unsigned char* msk  = (unsigned char*)(sm + SMEM_FLOATS);
    unsigned char* nbrt = msk + 27 * 28;

    int b   = blockIdx.x;
    int tid = threadIdx.x;

    // ---- embed (rows 27..31 zero) ----
    for (int idx = tid; idx < 32 * DMODEL; idx += THREADS) {
        int r = idx >> 8, cc = idx & 255;
        t[r * LDR + cc] = (r < NV)
            ? patch[b * NV + r] * w_in[cc] + b_in[cc] + pos[r * DMODEL + cc]
            : 0.0f;
    }

    // ---- per-patch neighbor table + mask ----
    int mode = g_mode;
    for (int idx = tid; idx < NV * NV; idx += THREADS) {
        int r = idx / NV, l = idx % NV;
        int zc = r / 9, yc = (r / 3) % 3, xc = r % 3;
        int z = zc + l / 9 - 1, y = yc + (l / 3) % 3 - 1, x = xc + l % 3 - 1;
        bool in = ((unsigned)z < 3u) && ((unsigned)y < 3u) && ((unsigned)x < 3u);
        int j = in ? (z * 9 + y * 3 + x) : 0;
        bool kv = false;
        if (in) {
            int gi = b * NV + j;
            if (mode == 0)      kv = ((const unsigned char*)km_raw)[gi] != 0;
            else if (mode == 1) kv = ((const int*)km_raw)[gi] != 0;
            else                kv = ((const float*)km_raw)[gi] != 0.0f;
        }
        msk[r * 28 + l]  = kv ? 1 : 0;
        nbrt[r * 28 + l] = (unsigned char)j;
    }
    __syncthreads();

    for (int l = 0; l < NLAYERS; l++) {
        int bb = l * 12;

        // LN1(t) -> ab ; Q from ab, K/V from raw t
        cta_ln(t, ln1_g + l * DMODEL, ln1_b + l * DMODEL, ab);
        __syncthreads();
        cta_gemm<0>(ab, bb + 0, bq + l * DMODEL, qb);
        cta_gemm<0>(t,  bb + 1, bk + l * DMODEL, kb);
        cta_gemm<0>(t,  bb + 2, bv + l * DMODEL, vb);

        cta_attn(qb, kb, vb, msk, nbrt, ab);
        __syncthreads();

        // t += ab @ Wo + bo
        cta_gemm<1>(ab, bb + 3, bo + l * DMODEL, t);

        // FFN: t += gelu(ln2(t) @ W1 + b1) @ W2 + b2, in 4 N-chunks of 256
        cta_ln(t, ln2_g + l * DMODEL, ln2_b + l * DMODEL, ab);
        __syncthreads();
        for (int cch = 0; cch < 4; cch++) {
            cta_gemm<2>(ab, bb + 4 + cch, b1 + l * FFDIM + cch * 256, qb);
            cta_gemm<1>(qb, bb + 8 + cch,
                        (cch == 0) ? (b2 + l * DMODEL) : g_zero, t);
        }
    }

    // ---- readout: out[b] = t[13] . w_out + b_out ----
    {
        float v = (tid < DMODEL) ? t[13 * LDR + tid] * w_out[tid] : 0.0f;
        #pragma unroll
        for (int off = 16; off > 0; off >>= 1)
            v += __shfl_xor_sync(0xffffffffu, v, off);
        if ((tid & 31) == 0 && tid < DMODEL) ab[tid >> 5] = v;
        __syncthreads();
        if (tid == 0) {
            float s = 0.0f;
            #pragma unroll
            for (int w = 0; w < 8; w++) s += ab[w];
            out[b] = s + b_out[0];
        }
    }
}

// ---------------- driver -----------------------------------------------------
extern "C" void kernel_launch(void* const* d_in, const int* in_sizes, int n_in,
                              void* d_out, int out_size) {
    const float* patch   = (const float*)d_in[0];
    const void*  km      = d_in[1];
    const float* w_in    = (const float*)d_in[2];
    const float* b_in    = (const float*)d_in[3];
    const float* pos     = (const float*)d_in[4];
    const float* ln1_g   = (const float*)d_in[5];
    const float* ln1_b   = (const float*)d_in[6];
    const float* ln2_g   = (const float*)d_in[7];
    const float* ln2_b   = (const float*)d_in[8];
    const float* Wq      = (const float*)d_in[9];
    const float* bq      = (const float*)d_in[10];
    const float* Wk      = (const float*)d_in[11];
    const float* bk      = (const float*)d_in[12];
    const float* Wv      = (const float*)d_in[13];
    const float* bv      = (const float*)d_in[14];
    const float* Wo      = (const float*)d_in[15];
    const float* bo      = (const float*)d_in[16];
    const float* W1      = (const float*)d_in[17];
    const float* b1      = (const float*)d_in[18];
    const float* W2      = (const float*)d_in[19];
    const float* b2      = (const float*)d_in[20];
    const float* w_out   = (const float*)d_in[21];
    const float* b_out   = (const float*)d_in[22];
    float* out = (float*)d_out;

    static int configured = 0;
    if (!configured) {
        cudaFuncSetAttribute(mega_kernel,
                             cudaFuncAttributeMaxDynamicSharedMemorySize,
                             SMEM_BYTES);
        configured = 1;
    }

    detect_kernel<<<1, 256>>>((const unsigned char*)km);
    repack_kernel<<<(36 * BLK_F4 + 255) / 256, 256>>>(Wq, Wk, Wv, Wo, W1, W2);
    mega_kernel<<<BATCH, THREADS, SMEM_BYTES>>>(
        patch, km, w_in, b_in, pos,
        ln1_g, ln1_b, ln2_g, ln2_b,
        bq, bk, bv, bo, b1, b2, w_out, b_out, out);
}

// round 17
// speedup vs baseline: 1.6049x; 1.6049x over previous
#include <cuda_runtime.h>
#include <math.h>

#define BATCH 256
#define NV 27
#define DMODEL 256
#define FFDIM 1024
#define NLAYERS 3
#define THREADS 512

#define LDR 260            // activation row pitch (floats)
#define OFF_T 0
#define OFF_A (32 * LDR)
#define OFF_Q (2 * 32 * LDR)
#define OFF_K (3 * 32 * LDR)
#define OFF_V (4 * 32 * LDR)
#define SMEM_FLOATS (5 * 32 * LDR)
#define SMEM_BYTES (SMEM_FLOATS * 4 + 2 * 27 * 28 + 64)

// 36 weight blocks of [256x256], fragment-packed (R15 512-thread mapping):
// float4 index within block: (ks2*16 + kt)*512 + tid
#define BLK_F4 16384
__device__ float4 g_wpack[36 * BLK_F4];
__device__ int    g_mode;
__device__ float  g_zero[DMODEL];      // zero-initialized

// ---------------- mask dtype sniffer ----------------------------------------
__global__ void detect_kernel(const unsigned char* __restrict__ km) {
    __shared__ int cnt1, cnt3f;
    if (threadIdx.x == 0) { cnt1 = 0; cnt3f = 0; }
    __syncthreads();
    int l1 = 0, l3 = 0;
    for (int i = threadIdx.x; i < (BATCH * NV) / 4; i += blockDim.x) {
        if (km[4 * i + 1] != 0) l1++;
        if (km[4 * i + 3] == 0x3F) l3++;
    }
    atomicAdd(&cnt1, l1);
    atomicAdd(&cnt3f, l3);
    __syncthreads();
    if (threadIdx.x == 0) {
        if (cnt1 > 0)       g_mode = 0;  // uint8 bool
        else if (cnt3f > 0) g_mode = 2;  // float32
        else                g_mode = 1;  // int32
    }
}

// ---------------- weight repack: [256x256] blocks -> fragment order ----------
__global__ void repack_kernel(const float* __restrict__ Wq,
                              const float* __restrict__ Wk,
                              const float* __restrict__ Wv,
                              const float* __restrict__ Wo,
                              const float* __restrict__ W1,
                              const float* __restrict__ W2) {
    int gid = blockIdx.x * 256 + threadIdx.x;       // 36*16384 = 589824 total
    if (gid >= 36 * BLK_F4) return;
    int blk = gid >> 14;
    int rem = gid & (BLK_F4 - 1);
    int ks2 = rem >> 13;
    int kt  = (rem >> 9) & 15;
    int tid = rem & 511;
    int layer = blk / 12, idx = blk % 12;

    const float* src;
    int ldB;
    if (idx < 4) {
        const float* base = (idx == 0) ? Wq : (idx == 1) ? Wk
                          : (idx == 2) ? Wv : Wo;
        src = base + (size_t)layer * DMODEL * DMODEL;
        ldB = DMODEL;
    } else if (idx < 8) {
        src = W1 + (size_t)layer * DMODEL * FFDIM + (idx - 4) * 256;
        ldB = FFDIM;
    } else {
        src = W2 + (size_t)layer * FFDIM * DMODEL + (size_t)(idx - 8) * 256 * DMODEL;
        ldB = DMODEL;
    }

    int warp = tid >> 5, lane = tid & 31;
    int grp = lane >> 2, quad = lane & 3;
    int krow = kt * 16 + ks2 * 8 + quad;
    int n0 = warp * 16 + grp;
    int n1 = n0 + 8;
    float4 v;
    v.x = src[(size_t)krow * ldB + n0];
    v.y = src[(size_t)(krow + 4) * ldB + n0];
    v.z = src[(size_t)krow * ldB + n1];
    v.w = src[(size_t)(krow + 4) * ldB + n1];
    g_wpack[gid] = v;
}

// ---------------- epilogue helper --------------------------------------------
template <int EPI>
__device__ __forceinline__ void epi_store(float* __restrict__ Cs,
                                          const float c[2][2][4],
                                          const float* __restrict__ bias,
                                          int warp, int grp, int quad) {
    #pragma unroll
    for (int mi = 0; mi < 2; mi++) {
        #pragma unroll
        for (int ni = 0; ni < 2; ni++) {
            int colb = warp * 16 + ni * 8 + quad * 2;
            float v0 = c[mi][ni][0] + bias[colb];
            float v1 = c[mi][ni][1] + bias[colb + 1];
            float v2 = c[mi][ni][2] + bias[colb];
            float v3 = c[mi][ni][3] + bias[colb + 1];
            int r0 = mi * 16 + grp;
            int r1 = r0 + 8;
            int i0 = r0 * LDR + colb;
            int i1 = r1 * LDR + colb;
            const float is2 = 0.70710678118654752f;
            if (EPI == 0) {
                Cs[i0] = v0; Cs[i0 + 1] = v1;
                Cs[i1] = v2; Cs[i1 + 1] = v3;
            } else if (EPI == 1) {
                Cs[i0] += v0; Cs[i0 + 1] += v1;
                Cs[i1] += v2; Cs[i1 + 1] += v3;
            } else {
                Cs[i0]     = 0.5f * v0 * (1.0f + erff(v0 * is2));
                Cs[i0 + 1] = 0.5f * v1 * (1.0f + erff(v1 * is2));
                Cs[i1]     = 0.5f * v2 * (1.0f + erff(v2 * is2));
                Cs[i1 + 1] = 0.5f * v3 * (1.0f + erff(v3 * is2));
            }
        }
    }
}

// ---------------- single-B CTA GEMM (R15, pre-epilogue barrier removed) ------
// PRECONDITION: C must not alias A (holds for every call in this schedule).
template <int EPI>
__device__ __noinline__ void cta_gemm(const float* __restrict__ Asm,
                                      int blk,
                                      const float* __restrict__ bias,
                                      float* __restrict__ Cs) {
    const float4* B0 = g_wpack + (size_t)blk * BLK_F4;
    const float4* B1 = B0 + 8192;

    int tid  = threadIdx.x;
    int lane = tid & 31;
    int warp = tid >> 5;
    int grp  = lane >> 2;
    int quad = lane & 3;

    float c[2][2][4];
    #pragma unroll
    for (int mi = 0; mi < 2; mi++)
        #pragma unroll
        for (int ni = 0; ni < 2; ni++)
            #pragma unroll
            for (int r = 0; r < 4; r++) c[mi][ni][r] = 0.0f;

    float4 pre0[2], pre1[2];
    pre0[0] = __ldg(B0 + tid);
    pre1[0] = __ldg(B1 + tid);
    pre0[1] = __ldg(B0 + 512 + tid);
    pre1[1] = __ldg(B1 + 512 + tid);

    #pragma unroll
    for (int kt = 0; kt < 16; kt++) {
        float4 v0 = pre0[kt & 1];
        float4 v1 = pre1[kt & 1];
        if (kt + 2 < 16) {
            pre0[kt & 1] = __ldg(B0 + (kt + 2) * 512 + tid);
            pre1[kt & 1] = __ldg(B1 + (kt + 2) * 512 + tid);
        }
        #pragma unroll
        for (int ks2 = 0; ks2 < 2; ks2++) {
            float4 v = ks2 ? v1 : v0;
            int kc = kt * 16 + ks2 * 8 + quad;
            #pragma unroll
            for (int mi = 0; mi < 2; mi++) {
                int m = mi * 16 + grp;
                unsigned a0 = __float_as_uint(Asm[m * LDR + kc]);
                unsigned a1 = __float_as_uint(Asm[(m + 8) * LDR + kc]);
                unsigned a2 = __float_as_uint(Asm[m * LDR + kc + 4]);
                unsigned a3 = __float_as_uint(Asm[(m + 8) * LDR + kc + 4]);
                asm volatile(
                    "mma.sync.aligned.m16n8k8.row.col.f32.tf32.tf32.f32 "
                    "{%0,%1,%2,%3}, {%4,%5,%6,%7}, {%8,%9}, {%0,%1,%2,%3};"
                    : "+f"(c[mi][0][0]), "+f"(c[mi][0][1]),
                      "+f"(c[mi][0][2]), "+f"(c[mi][0][3])
                    : "r"(a0), "r"(a1), "r"(a2), "r"(a3),
                      "r"(__float_as_uint(v.x)), "r"(__float_as_uint(v.y)));
                asm volatile(
                    "mma.sync.aligned.m16n8k8.row.col.f32.tf32.tf32.f32 "
                    "{%0,%1,%2,%3}, {%4,%5,%6,%7}, {%8,%9}, {%0,%1,%2,%3};"
                    : "+f"(c[mi][1][0]), "+f"(c[mi][1][1]),
                      "+f"(c[mi][1][2]), "+f"(c[mi][1][3])
                    : "r"(a0), "r"(a1), "r"(a2), "r"(a3),
                      "r"(__float_as_uint(v.z)), "r"(__float_as_uint(v.w)));
            }
        }
    }

    epi_store<EPI>(Cs, c, bias, warp, grp, quad);
    __syncthreads();
}

// ---------------- dual-B CTA GEMM: one A stream, two outputs ------------------
// PRECONDITION: C1/C2 do not alias A.
template <int EPI>
__device__ __noinline__ void cta_gemm2(const float* __restrict__ Asm,
                                       int blk1, int blk2,
                                       const float* __restrict__ bias1,
                                       const float* __restrict__ bias2,
                                       float* __restrict__ C1,
                                       float* __restrict__ C2) {
    const float4* X0 = g_wpack + (size_t)blk1 * BLK_F4;
    const float4* X1 = X0 + 8192;
    const float4* Y0 = g_wpack + (size_t)blk2 * BLK_F4;
    const float4* Y1 = Y0 + 8192;

    int tid  = threadIdx.x;
    int lane = tid & 31;
    int warp = tid >> 5;
    int grp  = lane >> 2;
    int quad = lane & 3;

    float cx[2][2][4], cy[2][2][4];
    #pragma unroll
    for (int mi = 0; mi < 2; mi++)
        #pragma unroll
        for (int ni = 0; ni < 2; ni++)
            #pragma unroll
            for (int r = 0; r < 4; r++) { cx[mi][ni][r] = 0.0f; cy[mi][ni][r] = 0.0f; }

    float4 px0[2], px1[2], py0[2], py1[2];
    px0[0] = __ldg(X0 + tid);        px1[0] = __ldg(X1 + tid);
    py0[0] = __ldg(Y0 + tid);        py1[0] = __ldg(Y1 + tid);
    px0[1] = __ldg(X0 + 512 + tid);  px1[1] = __ldg(X1 + 512 + tid);
    py0[1] = __ldg(Y0 + 512 + tid);  py1[1] = __ldg(Y1 + 512 + tid);

    #pragma unroll
    for (int kt = 0; kt < 16; kt++) {
        float4 vx0 = px0[kt & 1], vx1 = px1[kt & 1];
        float4 vy0 = py0[kt & 1], vy1 = py1[kt & 1];
        if (kt + 2 < 16) {
            px0[kt & 1] = __ldg(X0 + (kt + 2) * 512 + tid);
            px1[kt & 1] = __ldg(X1 + (kt + 2) * 512 + tid);
            py0[kt & 1] = __ldg(Y0 + (kt + 2) * 512 + tid);
            py1[kt & 1] = __ldg(Y1 + (kt + 2) * 512 + tid);
        }
        #pragma unroll
        for (int ks2 = 0; ks2 < 2; ks2++) {
            float4 vx = ks2 ? vx1 : vx0;
            float4 vy = ks2 ? vy1 : vy0;
            int kc = kt * 16 + ks2 * 8 + quad;
            #pragma unroll
            for (int mi = 0; mi < 2; mi++) {
                int m = mi * 16 + grp;
                unsigned a0 = __float_as_uint(Asm[m * LDR + kc]);
                unsigned a1 = __float_as_uint(Asm[(m + 8) * LDR + kc]);
                unsigned a2 = __float_as_uint(Asm[m * LDR + kc + 4]);
                unsigned a3 = __float_as_uint(Asm[(m + 8) * LDR + kc + 4]);
                asm volatile(
                    "mma.sync.aligned.m16n8k8.row.col.f32.tf32.tf32.f32 "
                    "{%0,%1,%2,%3}, {%4,%5,%6,%7}, {%8,%9}, {%0,%1,%2,%3};"
                    : "+f"(cx[mi][0][0]), "+f"(cx[mi][0][1]),
                      "+f"(cx[mi][0][2]), "+f"(cx[mi][0][3])
                    : "r"(a0), "r"(a1), "r"(a2), "r"(a3),
                      "r"(__float_as_uint(vx.x)), "r"(__float_as_uint(vx.y)));
                asm volatile(
                    "mma.sync.aligned.m16n8k8.row.col.f32.tf32.tf32.f32 "
                    "{%0,%1,%2,%3}, {%4,%5,%6,%7}, {%8,%9}, {%0,%1,%2,%3};"
                    : "+f"(cx[mi][1][0]), "+f"(cx[mi][1][1]),
                      "+f"(cx[mi][1][2]), "+f"(cx[mi][1][3])
                    : "r"(a0), "r"(a1), "r"(a2), "r"(a3),
                      "r"(__float_as_uint(vx.z)), "r"(__float_as_uint(vx.w)));
                asm volatile(
                    "mma.sync.aligned.m16n8k8.row.col.f32.tf32.tf32.f32 "
                    "{%0,%1,%2,%3}, {%4,%5,%6,%7}, {%8,%9}, {%0,%1,%2,%3};"
                    : "+f"(cy[mi][0][0]), "+f"(cy[mi][0][1]),
                      "+f"(cy[mi][0][2]), "+f"(cy[mi][0][3])
                    : "r"(a0), "r"(a1), "r"(a2), "r"(a3),
                      "r"(__float_as_uint(vy.x)), "r"(__float_as_uint(vy.y)));
                asm volatile(
                    "mma.sync.aligned.m16n8k8.row.col.f32.tf32.tf32.f32 "
                    "{%0,%1,%2,%3}, {%4,%5,%6,%7}, {%8,%9}, {%0,%1,%2,%3};"
                    : "+f"(cy[mi][1][0]), "+f"(cy[mi][1][1]),
                      "+f"(cy[mi][1][2]), "+f"(cy[mi][1][3])
                    : "r"(a0), "r"(a1), "r"(a2), "r"(a3),
                      "r"(__float_as_uint(vy.z)), "r"(__float_as_uint(vy.w)));
            }
        }
    }

    epi_store<EPI>(C1, cx, bias1, warp, grp, quad);
    epi_store<EPI>(C2, cy, bias2, warp, grp, quad);
    __syncthreads();
}

// ---------------- CTA layernorm: 32 rows, 16 warps (2 rows each) --------------
__device__ __forceinline__ void cta_ln(const float* __restrict__ x,
                                       const float* __restrict__ g,
                                       const float* __restrict__ bta,
                                       float* __restrict__ y) {
    int tid = threadIdx.x, warp = tid >> 5, lane = tid & 31;
    #pragma unroll
    for (int it = 0; it < 2; it++) {
        int r = warp + it * 16;
        const float* xr = x + r * LDR + lane * 8;
        float4 v0 = *(const float4*)&xr[0];
        float4 v1 = *(const float4*)&xr[4];
        float s  = v0.x + v0.y + v0.z + v0.w + v1.x + v1.y + v1.z + v1.w;
        float ss = v0.x*v0.x + v0.y*v0.y + v0.z*v0.z + v0.w*v0.w
                 + v1.x*v1.x + v1.y*v1.y + v1.z*v1.z + v1.w*v1.w;
        #pragma unroll
        for (int off = 16; off > 0; off >>= 1) {
            s  += __shfl_xor_sync(0xffffffffu, s,  off);
            ss += __shfl_xor_sync(0xffffffffu, ss, off);
        }
        float mu  = s * (1.0f / DMODEL);
        float var = ss * (1.0f / DMODEL) - mu * mu;
        float rs  = rsqrtf(var + 1e-5f);
        float* yr = y + r * LDR;
        #pragma unroll
        for (int j = 0; j < 8; j++) {
            int cc = lane * 8 + j;
            float xv = (j < 4) ? ((const float*)&v0)[j] : ((const float*)&v1)[j - 4];
            yr[cc] = (xv - mu) * rs * g[cc] + bta[cc];
        }
    }
}

// ---------------- attention (first 8 warps): warp per head --------------------
__device__ __noinline__ void cta_attn(const float* __restrict__ qb,
                                      const float* __restrict__ kb,
                                      const float* __restrict__ vb,
                                      const unsigned char* __restrict__ msk,
                                      const unsigned char* __restrict__ nbrt,
                                      float* __restrict__ ab) {
    int tid = threadIdx.x;
    if (tid >= 256) return;
    int h = tid >> 5;
    int r = tid & 31;
    const float scale = 0.17677669529663687f;  // 1/sqrt(32)

    float4 q4[8];
    if (r < NV) {
        #pragma unroll
        for (int i = 0; i < 8; i++)
            q4[i] = *(const float4*)&qb[r * LDR + h * 32 + i * 4];
    }
    float s[NV];
    float mx = -1e30f;
    #pragma unroll
    for (int l = 0; l < NV; l++) {
        s[l] = -1e30f;
        if (r < NV && msk[r * 28 + l]) {
            int j = nbrt[r * 28 + l];
            const float* kr = &kb[j * LDR + h * 32];
            float acc = 0.0f;
            #pragma unroll
            for (int i = 0; i < 8; i++) {
                float4 k4 = *(const float4*)&kr[i * 4];
                acc += q4[i].x * k4.x + q4[i].y * k4.y
                     + q4[i].z * k4.z + q4[i].w * k4.w;
            }
            s[l] = acc * scale;
            mx = fmaxf(mx, s[l]);
        }
    }
    float sum = 0.0f;
    #pragma unroll
    for (int l = 0; l < NV; l++) {
        float w = (s[l] > -1e29f) ? expf(s[l] - mx) : 0.0f;
        s[l] = w;
        sum += w;
    }
    float inv = (sum > 0.0f) ? (1.0f / sum) : 0.0f;

    float4 f4[8];
    #pragma unroll
    for (int i = 0; i < 8; i++) f4[i] = make_float4(0.f, 0.f, 0.f, 0.f);
    #pragma unroll
    for (int l = 0; l < NV; l++) {
        if (s[l] > 0.0f) {
            int j = nbrt[r * 28 + l];
            const float* vr = &vb[j * LDR + h * 32];
            float w = s[l];
            #pragma unroll
            for (int i = 0; i < 8; i++) {
                float4 v4 = *(const float4*)&vr[i * 4];
                f4[i].x += w * v4.x; f4[i].y += w * v4.y;
                f4[i].z += w * v4.z; f4[i].w += w * v4.w;
            }
        }
    }
    if (r < NV) {
        #pragma unroll
        for (int i = 0; i < 8; i++) {
            float4 o = make_float4(f4[i].x * inv, f4[i].y * inv,
                                   f4[i].z * inv, f4[i].w * inv);
            *(float4*)&ab[r * LDR + h * 32 + i * 4] = o;
        }
    }
}

// ---------------- megakernel: one CTA per patch -------------------------------
__global__ void __launch_bounds__(THREADS, 1)
mega_kernel(const float* __restrict__ patch, const void* __restrict__ km_raw,
            const float* __restrict__ w_in, const float* __restrict__ b_in,
            const float* __restrict__ pos,
            const float* __restrict__ ln1_g, const float* __restrict__ ln1_b,
            const float* __restrict__ ln2_g, const float* __restrict__ ln2_b,
            const float* __restrict__ bq, const float* __restrict__ bk,
            const float* __restrict__ bv, const float* __restrict__ bo,
            const float* __restrict__ b1, const float* __restrict__ b2,
            const float* __restrict__ w_out, const float* __restrict__ b_out,
            float* __restrict__ out) {
    extern __shared__ float sm[];
    float* t  = sm + OFF_T;
    float* ab = sm + OFF_A;
    float* qb = sm + OFF_Q;
    float* kb = sm + OFF_K;
    float* vb = sm + OFF_V;
    unsigned char* msk  = (unsigned char*)(sm + SMEM_FLOATS);
    unsigned char* nbrt = msk + 27 * 28;

    int b   = blockIdx.x;
    int tid = threadIdx.x;

    // ---- embed (rows 27..31 zero) ----
    for (int idx = tid; idx < 32 * DMODEL; idx += THREADS) {
        int r = idx >> 8, cc = idx & 255;
        t[r * LDR + cc] = (r < NV)
            ? patch[b * NV + r] * w_in[cc] + b_in[cc] + pos[r * DMODEL + cc]
            : 0.0f;
    }

    // ---- per-patch neighbor table + mask ----
    int mode = g_mode;
    for (int idx = tid; idx < NV * NV; idx += THREADS) {
        int r = idx / NV, l = idx % NV;
        int zc = r / 9, yc = (r / 3) % 3, xc = r % 3;
        int z = zc + l / 9 - 1, y = yc + (l / 3) % 3 - 1, x = xc + l % 3 - 1;
        bool in = ((unsigned)z < 3u) && ((unsigned)y < 3u) && ((unsigned)x < 3u);
        int j = in ? (z * 9 + y * 3 + x) : 0;
        bool kv = false;
        if (in) {
            int gi = b * NV + j;
            if (mode == 0)      kv = ((const unsigned char*)km_raw)[gi] != 0;
            else if (mode == 1) kv = ((const int*)km_raw)[gi] != 0;
            else                kv = ((const float*)km_raw)[gi] != 0.0f;
        }
        msk[r * 28 + l]  = kv ? 1 : 0;
        nbrt[r * 28 + l] = (unsigned char)j;
    }
    __syncthreads();

    for (int l = 0; l < NLAYERS; l++) {
        int bb = l * 12;

        // LN1(t) -> ab ; Q from ab ; K,V fused dual-B from raw t
        cta_ln(t, ln1_g + l * DMODEL, ln1_b + l * DMODEL, ab);
        __syncthreads();
        cta_gemm<0>(ab, bb + 0, bq + l * DMODEL, qb);
        cta_gemm2<0>(t, bb + 1, bb + 2, bk + l * DMODEL, bv + l * DMODEL,
                     kb, vb);

        cta_attn(qb, kb, vb, msk, nbrt, ab);
        __syncthreads();

        // t += ab @ Wo + bo
        cta_gemm<1>(ab, bb + 3, bo + l * DMODEL, t);

        // FFN: LN2 -> ab ; W1 chunk-pairs fused (A=ab shared) -> qb,kb ;
        // then W2 per chunk accumulates into t.
        cta_ln(t, ln2_g + l * DMODEL, ln2_b + l * DMODEL, ab);
        __syncthreads();
        #pragma unroll
        for (int pair = 0; pair < 2; pair++) {
            int c0 = pair * 2, c1 = c0 + 1;
            cta_gemm2<2>(ab, bb + 4 + c0, bb + 4 + c1,
                         b1 + l * FFDIM + c0 * 256, b1 + l * FFDIM + c1 * 256,
                         qb, kb);
            cta_gemm<1>(qb, bb + 8 + c0,
                        (c0 == 0) ? (b2 + l * DMODEL) : g_zero, t);
            cta_gemm<1>(kb, bb + 8 + c1, g_zero, t);
        }
    }

    // ---- readout: out[b] = t[13] . w_out + b_out ----
    {
        float v = (tid < DMODEL) ? t[13 * LDR + tid] * w_out[tid] : 0.0f;
        #pragma unroll
        for (int off = 16; off > 0; off >>= 1)
            v += __shfl_xor_sync(0xffffffffu, v, off);
        if ((tid & 31) == 0 && tid < DMODEL) ab[tid >> 5] = v;
        __syncthreads();
        if (tid == 0) {
            float s = 0.0f;
            #pragma unroll
            for (int w = 0; w < 8; w++) s += ab[w];
            out[b] = s + b_out[0];
        }
    }
}

// ---------------- driver -----------------------------------------------------
extern "C" void kernel_launch(void* const* d_in, const int* in_sizes, int n_in,
                              void* d_out, int out_size) {
    const float* patch   = (const float*)d_in[0];
    const void*  km      = d_in[1];
    const float* w_in    = (const float*)d_in[2];
    const float* b_in    = (const float*)d_in[3];
    const float* pos     = (const float*)d_in[4];
    const float* ln1_g   = (const float*)d_in[5];
    const float* ln1_b   = (const float*)d_in[6];
    const float* ln2_g   = (const float*)d_in[7];
    const float* ln2_b   = (const float*)d_in[8];
    const float* Wq      = (const float*)d_in[9];
    const float* bq      = (const float*)d_in[10];
    const float* Wk      = (const float*)d_in[11];
    const float* bk      = (const float*)d_in[12];
    const float* Wv      = (const float*)d_in[13];
    const float* bv      = (const float*)d_in[14];
    const float* Wo      = (const float*)d_in[15];
    const float* bo      = (const float*)d_in[16];
    const float* W1      = (const float*)d_in[17];
    const float* b1      = (const float*)d_in[18];
    const float* W2      = (const float*)d_in[19];
    const float* b2      = (const float*)d_in[20];
    const float* w_out   = (const float*)d_in[21];
    const float* b_out   = (const float*)d_in[22];
    float* out = (float*)d_out;

    static int configured = 0;
    if (!configured) {
        cudaFuncSetAttribute(mega_kernel,
                             cudaFuncAttributeMaxDynamicSharedMemorySize,
                             SMEM_BYTES);
        configured = 1;
    }

    detect_kernel<<<1, 256>>>((const unsigned char*)km);
    repack_kernel<<<(36 * BLK_F4 + 255) / 256, 256>>>(Wq, Wk, Wv, Wo, W1, W2);
    mega_kernel<<<BATCH, THREADS, SMEM_BYTES>>>(
        patch, km, w_in, b_in, pos,
        ln1_g, ln1_b, ln2_g, ln2_b,
        bq, bk, bv, bo, b1, b2, w_out, b_out, out);
}